// round 8
// baseline (speedup 1.0000x reference)
#include <cuda_runtime.h>
#include <cuda_bf16.h>

// Problem constants
#define TT 512
#define BB 64
#define DD 1024
#define HH 1024
#define NBLK 128
#define NTHR 512

typedef unsigned long long ull;

// SMEM layout for scan (floats)
#define SM_W        32768                         // wsm: [1024][32] (k-pair interleaved)
#define HST_U64_W   384                           // per warp: 2 bufs x 32 k x 6 u64
#define SM_RED      (SM_W + 16 * HST_U64_W * 2)   // 32768 + 12288 = 45056  (u64 -> floats: x2)
#define SM_TOT_F    (SM_RED + 8 * 512)            // 49152 floats
#define SM_TOT_B    (SM_TOT_F * 4)                // 196608 bytes (< 227 KB opt-in)

// Group-barrier slots: 4 groups x 32 blocks, each padded to 32 B
__device__ unsigned g_arr[4 * 32 * 8];

// ---------------------------------------------------------------------------
// f32x2 helpers
// ---------------------------------------------------------------------------
__device__ __forceinline__ ull fma2(ull a, ull b, ull c) {
    ull d;
    asm("fma.rn.f32x2 %0, %1, %2, %3;" : "=l"(d) : "l"(a), "l"(b), "l"(c));
    return d;
}
__device__ __forceinline__ ull pack2(float x, float y) {
    ull d; asm("mov.b64 %0, {%1, %2};" : "=l"(d) : "f"(x), "f"(y)); return d;
}
__device__ __forceinline__ void unpack2(ull v, float& x, float& y) {
    asm("mov.b64 {%0, %1}, %2;" : "=f"(x), "=f"(y) : "l"(v));
}

// ---------------------------------------------------------------------------
// Kernel 1: xproj = inputs @ W_xh + b (FFMA2). Block (0,0) zeroes flags.
// ---------------------------------------------------------------------------
__global__ __launch_bounds__(256) void xproj_kernel(
    const float* __restrict__ A,      // [32768, 1024]
    const float* __restrict__ W,      // [1024, 1024]
    const float* __restrict__ bias,   // [1024]
    float* __restrict__ out)          // [32768, 1024]
{
    __shared__ float As[16][128];
    __shared__ float Bs[16][64];

    const int bm  = blockIdx.y * 128;
    const int bn  = blockIdx.x * 64;
    const int tid = threadIdx.x;
    const int tx  = tid & 15;
    const int ty  = tid >> 4;

    if (blockIdx.x == 0 && blockIdx.y == 0) {
        for (int i = tid; i < 4 * 32 * 8; i += 256) g_arr[i] = 0u;
    }

    ull acc[4][4];
#pragma unroll
    for (int p = 0; p < 4; p++)
#pragma unroll
        for (int j = 0; j < 4; j++) acc[p][j] = 0ull;

    const int r_ld  = tid >> 1;
    const int kq_ld = (tid & 1) * 2;
    const int kk_ld = tid >> 4;
    const int cq_ld = tid & 15;

    for (int k0 = 0; k0 < DD; k0 += 16) {
#pragma unroll
        for (int i = 0; i < 2; i++) {
            float4 v = *(const float4*)&A[(size_t)(bm + r_ld) * DD + k0 + (kq_ld + i) * 4];
            As[(kq_ld + i) * 4 + 0][r_ld] = v.x;
            As[(kq_ld + i) * 4 + 1][r_ld] = v.y;
            As[(kq_ld + i) * 4 + 2][r_ld] = v.z;
            As[(kq_ld + i) * 4 + 3][r_ld] = v.w;
        }
        {
            float4 v = *(const float4*)&W[(size_t)(k0 + kk_ld) * HH + bn + cq_ld * 4];
            *(float4*)&Bs[kk_ld][cq_ld * 4] = v;
        }
        __syncthreads();

#pragma unroll
        for (int kk = 0; kk < 16; kk++) {
            ulonglong2 a0 = *(const ulonglong2*)&As[kk][ty * 8];
            ulonglong2 a1 = *(const ulonglong2*)&As[kk][ty * 8 + 4];
            float4 bq = *(const float4*)&Bs[kk][tx * 4];
            ull b0 = pack2(bq.x, bq.x);
            ull b1 = pack2(bq.y, bq.y);
            ull b2 = pack2(bq.z, bq.z);
            ull b3 = pack2(bq.w, bq.w);
            ull av[4] = {a0.x, a0.y, a1.x, a1.y};
#pragma unroll
            for (int p = 0; p < 4; p++) {
                acc[p][0] = fma2(av[p], b0, acc[p][0]);
                acc[p][1] = fma2(av[p], b1, acc[p][1]);
                acc[p][2] = fma2(av[p], b2, acc[p][2]);
                acc[p][3] = fma2(av[p], b3, acc[p][3]);
            }
        }
        __syncthreads();
    }

    float4 bv;
    bv.x = bias[bn + tx * 4 + 0];
    bv.y = bias[bn + tx * 4 + 1];
    bv.z = bias[bn + tx * 4 + 2];
    bv.w = bias[bn + tx * 4 + 3];
#pragma unroll
    for (int p = 0; p < 4; p++) {
        float lo0, hi0, lo1, hi1, lo2, hi2, lo3, hi3;
        unpack2(acc[p][0], lo0, hi0);
        unpack2(acc[p][1], lo1, hi1);
        unpack2(acc[p][2], lo2, hi2);
        unpack2(acc[p][3], lo3, hi3);
        int row0 = bm + ty * 8 + 2 * p;
        float4 o0; o0.x = lo0 + bv.x; o0.y = lo1 + bv.y; o0.z = lo2 + bv.z; o0.w = lo3 + bv.w;
        float4 o1; o1.x = hi0 + bv.x; o1.y = hi1 + bv.y; o1.z = hi2 + bv.z; o1.w = hi3 + bv.w;
        *(float4*)&out[(size_t)row0 * HH + bn + tx * 4] = o0;
        *(float4*)&out[(size_t)(row0 + 1) * HH + bn + tx * 4] = o1;
    }
}

// ---------------------------------------------------------------------------
// Kernel 2: persistent scan, 512 threads/block (16 warps).
// Block (rq,ct): rows rq*16..+15, cols ct*32..+31.
// Warp (s,rg): s = wid&7 -> K slice of 128 (4 chunks of 32 k); rg = wid>>3.
// w in SMEM as interleaved k-pairs -> LDS.64 serves 2 k.
// ---------------------------------------------------------------------------
__global__ __launch_bounds__(NTHR, 1) void scan_kernel(
    const float* __restrict__ state,   // [64, 1024]
    const float* __restrict__ Whh,     // [1024, 1024]
    float* __restrict__ out,           // d_out
    int write_final)
{
    extern __shared__ float sm[];
    float* wsm    = sm;                        // k-pair interleaved [512][32][2]
    ull*   hstAll = (ull*)(sm + SM_W);         // 16 warps x 384 u64 = [32768, 45056) floats
    float* red    = sm + SM_RED;               // [8][512] = [45056, 49152)

    const int bid = blockIdx.x;
    const int tid = threadIdx.x;
    const int rq  = bid >> 5;
    const int ct  = bid & 31;

    const int lane = tid & 31;
    const int wid  = tid >> 5;
    const int s    = wid & 7;          // K slice: [s*128, s*128+128)
    const int rg   = wid >> 3;         // rows rg*8 .. +7 (within quad)

    // W slice, interleaved k-pairs: wsm[((k>>1)*32 + c)*2 + (k&1)]
    for (int i = tid; i < 1024 * 32; i += NTHR) {
        int k = i >> 5, c = i & 31;
        wsm[(((k >> 1) * 32) + c) * 2 + (k & 1)] = Whh[(size_t)k * HH + ct * 32 + c];
    }

    const int R0 = rq * 16 + rg * 8;
    const int k4 = lane & 7;
    const int rr = lane >> 3;
    ull* myhst = hstAll + wid * HST_U64_W;

    const int o0 = tid;
    const int gidx0 = (rq * 16 + (o0 >> 5)) * HH + ct * 32 + (o0 & 31);

    unsigned* myslot   = &g_arr[(rq * 32 + ct) * 8];
    const unsigned* po = &g_arr[(rq * 32 + lane) * 8];

    __syncthreads();

    float xp0 = out[gidx0];    // xp for step 0

    for (int t = 0; t < TT; t++) {
        const float* hsrc = (t == 0) ? state : (out + (size_t)(t - 1) * BB * HH);
        float* xp = out + (size_t)t * BB * HH;

        ull acc0 = 0, acc1 = 0, acc2 = 0, acc3 = 0;

        const float* src = &hsrc[(size_t)(R0 + rr) * HH + s * 128 + k4 * 4];
        float4 v0 = __ldcg((const float4*)src);
        float4 v1 = __ldcg((const float4*)(src + 4 * HH));
        int b = 0;

#pragma unroll 1
        for (int ci = 0; ci < 4; ci++) {
            float4 u0, u1;
            if (ci < 3) {   // prefetch next chunk
                const float* s2 = src + (ci + 1) * 32;
                u0 = __ldcg((const float4*)s2);
                u1 = __ldcg((const float4*)(s2 + 4 * HH));
            }
            // stage current chunk: pack rows (rr, rr+4) as f32x2
            {
                ull* d = myhst + b * 192 + (k4 * 4) * 6 + rr;
                d[0]  = pack2(v0.x, v1.x);
                d[6]  = pack2(v0.y, v1.y);
                d[12] = pack2(v0.z, v1.z);
                d[18] = pack2(v0.w, v1.w);
            }
            __syncwarp();
            // compute chunk: k-pairs, 1 LDS.64 (w) + 4 LDS.128 (h) + 8 FFMA2
            {
                const int kb = s * 128 + ci * 32;     // chunk base k
                const float2* wpb = ((const float2*)wsm) + kb * 16 + lane;
                const ulonglong2* hb = (const ulonglong2*)(myhst + b * 192);
#pragma unroll
                for (int kk = 0; kk < 16; kk++) {
                    float2 wp = wpb[kk * 32];
                    ull w2a = pack2(wp.x, wp.x);
                    ull w2b = pack2(wp.y, wp.y);
                    ulonglong2 hA0 = hb[(2 * kk) * 3];
                    ulonglong2 hB0 = hb[(2 * kk) * 3 + 1];
                    ulonglong2 hA1 = hb[(2 * kk + 1) * 3];
                    ulonglong2 hB1 = hb[(2 * kk + 1) * 3 + 1];
                    acc0 = fma2(hA0.x, w2a, acc0);
                    acc1 = fma2(hA0.y, w2a, acc1);
                    acc2 = fma2(hB0.x, w2a, acc2);
                    acc3 = fma2(hB0.y, w2a, acc3);
                    acc0 = fma2(hA1.x, w2b, acc0);
                    acc1 = fma2(hA1.y, w2b, acc1);
                    acc2 = fma2(hB1.x, w2b, acc2);
                    acc3 = fma2(hB1.y, w2b, acc3);
                }
            }
            v0 = u0; v1 = u1; b ^= 1;
        }

        // intra-block split-K (8-way) reduce through SMEM
        {
            float lo, hi;
            unpack2(acc0, lo, hi);
            red[s * 512 + (rg * 8 + 0) * 32 + lane] = lo;
            red[s * 512 + (rg * 8 + 4) * 32 + lane] = hi;
            unpack2(acc1, lo, hi);
            red[s * 512 + (rg * 8 + 1) * 32 + lane] = lo;
            red[s * 512 + (rg * 8 + 5) * 32 + lane] = hi;
            unpack2(acc2, lo, hi);
            red[s * 512 + (rg * 8 + 2) * 32 + lane] = lo;
            red[s * 512 + (rg * 8 + 6) * 32 + lane] = hi;
            unpack2(acc3, lo, hi);
            red[s * 512 + (rg * 8 + 3) * 32 + lane] = lo;
            red[s * 512 + (rg * 8 + 7) * 32 + lane] = hi;
        }
        __syncthreads();

        // phase 2: sum 8 slices + xp, tanh, write h_t over xp_t (1 out/thread)
        {
            float vv = xp0;
#pragma unroll
            for (int q = 0; q < 8; q++) vv += red[q * 512 + o0];
            float h0 = tanhf(vv);
            xp[gidx0] = h0;
            if (write_final && t == TT - 1)
                out[(size_t)TT * BB * HH + gidx0] = h0;
        }

        if (t < TT - 1) {
            __syncthreads();   // all h_t STGs of this block done
            if (tid == 0)
                asm volatile("st.release.gpu.global.b32 [%0], %1;"
                             :: "l"(myslot), "r"((unsigned)(t + 1)));
            xp0 = xp[BB * HH + gidx0];   // prefetch next xp during wait
            if (wid == 0) {
                unsigned v;
                do {
                    asm volatile("ld.acquire.gpu.global.b32 %0, [%1];"
                                 : "=r"(v) : "l"(po));
                } while (!__all_sync(0xffffffffu, v > (unsigned)t));
            }
            __syncthreads();
        }
    }
}

// ---------------------------------------------------------------------------
extern "C" void kernel_launch(void* const* d_in, const int* in_sizes, int n_in,
                              void* d_out, int out_size) {
    const float* inputs = (const float*)d_in[0];   // [T,B,D]
    const float* state  = (const float*)d_in[1];   // [B,H]
    const float* W_xh   = (const float*)d_in[2];   // [D,H]
    const float* W_hh   = (const float*)d_in[3];   // [H,H]
    const float* b_h    = (const float*)d_in[4];   // [H]
    float* out = (float*)d_out;

    int write_final = (out_size >= TT * BB * HH + BB * HH) ? 1 : 0;

    static int smem_set = 0;
    if (!smem_set) {
        cudaFuncSetAttribute(scan_kernel,
                             cudaFuncAttributeMaxDynamicSharedMemorySize,
                             SM_TOT_B);
        smem_set = 1;
    }

    dim3 g1(HH / 64, (TT * BB) / 128);
    xproj_kernel<<<g1, 256>>>(inputs, W_xh, b_h, out);

    scan_kernel<<<NBLK, NTHR, SM_TOT_B>>>(state, W_hh, out, write_final);
}

// round 10
// speedup vs baseline: 1.2276x; 1.2276x over previous
#include <cuda_runtime.h>
#include <cuda_bf16.h>

// Problem constants
#define TT 512
#define BB 64
#define DD 1024
#define HH 1024
#define NBLK 128
#define NTHR 256

typedef unsigned long long ull;

// SMEM layout for scan (floats)
#define SM_W      32768                 // wsm [1024][32]                 [0,32768)
#define SM_HST    32768                 // hst: 8 warps x 2 buf x 256 u64 [32768,40960)
#define SM_RED    40960                 // red [8][512]                   [40960,45056)
#define SM_TOT_F  45056
#define SM_TOT_B  (SM_TOT_F * 4)        // 180224 B < 227 KB

// Group-barrier slots: 4 groups x 32 blocks, padded to 32 B
__device__ unsigned g_arr[4 * 32 * 8];

// ---------------------------------------------------------------------------
// f32x2 helpers
// ---------------------------------------------------------------------------
__device__ __forceinline__ ull fma2(ull a, ull b, ull c) {
    ull d;
    asm("fma.rn.f32x2 %0, %1, %2, %3;" : "=l"(d) : "l"(a), "l"(b), "l"(c));
    return d;
}
__device__ __forceinline__ ull pack2(float x, float y) {
    ull d; asm("mov.b64 %0, {%1, %2};" : "=l"(d) : "f"(x), "f"(y)); return d;
}
__device__ __forceinline__ void unpack2(ull v, float& x, float& y) {
    asm("mov.b64 {%0, %1}, %2;" : "=f"(x), "=f"(y) : "l"(v));
}

// ---------------------------------------------------------------------------
// Kernel 1: xproj = inputs @ W_xh + b (FFMA2). Block (0,0) zeroes flags.
// ---------------------------------------------------------------------------
__global__ __launch_bounds__(256) void xproj_kernel(
    const float* __restrict__ A,      // [32768, 1024]
    const float* __restrict__ W,      // [1024, 1024]
    const float* __restrict__ bias,   // [1024]
    float* __restrict__ out)          // [32768, 1024]
{
    __shared__ float As[16][128];
    __shared__ float Bs[16][64];

    const int bm  = blockIdx.y * 128;
    const int bn  = blockIdx.x * 64;
    const int tid = threadIdx.x;
    const int tx  = tid & 15;
    const int ty  = tid >> 4;

    if (blockIdx.x == 0 && blockIdx.y == 0) {
        for (int i = tid; i < 4 * 32 * 8; i += 256) g_arr[i] = 0u;
    }

    ull acc[4][4];
#pragma unroll
    for (int p = 0; p < 4; p++)
#pragma unroll
        for (int j = 0; j < 4; j++) acc[p][j] = 0ull;

    const int r_ld  = tid >> 1;
    const int kq_ld = (tid & 1) * 2;
    const int kk_ld = tid >> 4;
    const int cq_ld = tid & 15;

    for (int k0 = 0; k0 < DD; k0 += 16) {
#pragma unroll
        for (int i = 0; i < 2; i++) {
            float4 v = *(const float4*)&A[(size_t)(bm + r_ld) * DD + k0 + (kq_ld + i) * 4];
            As[(kq_ld + i) * 4 + 0][r_ld] = v.x;
            As[(kq_ld + i) * 4 + 1][r_ld] = v.y;
            As[(kq_ld + i) * 4 + 2][r_ld] = v.z;
            As[(kq_ld + i) * 4 + 3][r_ld] = v.w;
        }
        {
            float4 v = *(const float4*)&W[(size_t)(k0 + kk_ld) * HH + bn + cq_ld * 4];
            *(float4*)&Bs[kk_ld][cq_ld * 4] = v;
        }
        __syncthreads();

#pragma unroll
        for (int kk = 0; kk < 16; kk++) {
            ulonglong2 a0 = *(const ulonglong2*)&As[kk][ty * 8];
            ulonglong2 a1 = *(const ulonglong2*)&As[kk][ty * 8 + 4];
            float4 bq = *(const float4*)&Bs[kk][tx * 4];
            ull b0 = pack2(bq.x, bq.x);
            ull b1 = pack2(bq.y, bq.y);
            ull b2 = pack2(bq.z, bq.z);
            ull b3 = pack2(bq.w, bq.w);
            ull av[4] = {a0.x, a0.y, a1.x, a1.y};
#pragma unroll
            for (int p = 0; p < 4; p++) {
                acc[p][0] = fma2(av[p], b0, acc[p][0]);
                acc[p][1] = fma2(av[p], b1, acc[p][1]);
                acc[p][2] = fma2(av[p], b2, acc[p][2]);
                acc[p][3] = fma2(av[p], b3, acc[p][3]);
            }
        }
        __syncthreads();
    }

    float4 bv;
    bv.x = bias[bn + tx * 4 + 0];
    bv.y = bias[bn + tx * 4 + 1];
    bv.z = bias[bn + tx * 4 + 2];
    bv.w = bias[bn + tx * 4 + 3];
#pragma unroll
    for (int p = 0; p < 4; p++) {
        float lo0, hi0, lo1, hi1, lo2, hi2, lo3, hi3;
        unpack2(acc[p][0], lo0, hi0);
        unpack2(acc[p][1], lo1, hi1);
        unpack2(acc[p][2], lo2, hi2);
        unpack2(acc[p][3], lo3, hi3);
        int row0 = bm + ty * 8 + 2 * p;
        float4 o0; o0.x = lo0 + bv.x; o0.y = lo1 + bv.y; o0.z = lo2 + bv.z; o0.w = lo3 + bv.w;
        float4 o1; o1.x = hi0 + bv.x; o1.y = hi1 + bv.y; o1.z = hi2 + bv.z; o1.w = hi3 + bv.w;
        *(float4*)&out[(size_t)row0 * HH + bn + tx * 4] = o0;
        *(float4*)&out[(size_t)(row0 + 1) * HH + bn + tx * 4] = o1;
    }
}

// ---------------------------------------------------------------------------
// Kernel 2: persistent scan, 256 threads (8 warps).
// Block (rq,ct): rows rq*16..+15, cols ct*32..+31. Warp wid = K slice of 128.
// Each warp computes the FULL 16x32 tile over its K slice:
//   lane = (cg = lane&15 -> colpair 2cg..2cg+1, rg2 = lane>>4 -> rows rg2*8..+7)
// hst per warp per k: 8 u64 (row pairs (j, j+4)), 16B-slot-swizzled by (k>>2)&3.
// Inner loop per k: 2 LDS.128 (h) + 1 LDS.64 (w) + 2 pack + 8 FFMA2.
// ---------------------------------------------------------------------------
__global__ __launch_bounds__(NTHR, 1) void scan_kernel(
    const float* __restrict__ state,   // [64, 1024]
    const float* __restrict__ Whh,     // [1024, 1024]
    float* __restrict__ out,           // d_out
    int write_final)
{
    extern __shared__ float sm[];
    float* wsm    = sm;                        // [1024][32]
    ull*   hstAll = (ull*)(sm + SM_HST);       // 8 warps x 512 u64
    float* red    = sm + SM_RED;               // [8][512]

    const int bid = blockIdx.x;
    const int tid = threadIdx.x;
    const int rq  = bid >> 5;
    const int ct  = bid & 31;

    const int lane = tid & 31;
    const int wid  = tid >> 5;         // = K slice s (8 slices of 128 k)

    const int cg  = lane & 15;         // colpair: cols 2cg, 2cg+1
    const int rg2 = lane >> 4;         // row octet: rows rg2*8 .. +7

    // W slice: wsm[k*32 + c]
    for (int i = tid; i < 1024 * 32; i += NTHR)
        wsm[i] = Whh[(size_t)(i >> 5) * HH + ct * 32 + (i & 31)];

    const int R0 = rq * 16;
    // staging lane decomposition
    const int k4 = lane & 7;           // float4 index along k (k = k4*4+e)
    const int r0 = lane >> 3;          // 0..3: rows r0, r0+4, r0+8, r0+12
    ull* hw = hstAll + wid * 512;      // 2 bufs x 256 u64

    // swizzled 16B-slot byte offsets for the compute reads (m = (kk>>2)&3)
    int offA[4], offB[4];
#pragma unroll
    for (int m = 0; m < 4; m++) {
        offA[m] = (((rg2 * 2) ^ m)) * 2;       // u64 units
        offB[m] = (((rg2 * 2 + 1) ^ m)) * 2;
    }
    const int swq = k4 & 3;            // writer's slot XOR key
    const int q0w = ((r0 >> 1) ^ swq) * 2 + (r0 & 1);        // u64 offset, octet0
    const int q1w = ((2 + (r0 >> 1)) ^ swq) * 2 + (r0 & 1);  // octet1

    const int o0 = tid, o1 = tid + 256;
    const int gidx0 = (R0 + (o0 >> 5)) * HH + ct * 32 + (o0 & 31);
    const int gidx1 = (R0 + (o1 >> 5)) * HH + ct * 32 + (o1 & 31);

    unsigned* myslot   = &g_arr[(rq * 32 + ct) * 8];
    const unsigned* po = &g_arr[(rq * 32 + lane) * 8];

    __syncthreads();

    float xp0 = out[gidx0];    // xp for step 0
    float xp1 = out[gidx1];

    for (int t = 0; t < TT; t++) {
        const float* hsrc = (t == 0) ? state : (out + (size_t)(t - 1) * BB * HH);
        float* xp = out + (size_t)t * BB * HH;

        ull acc[2][4];
#pragma unroll
        for (int c = 0; c < 2; c++)
#pragma unroll
            for (int j = 0; j < 4; j++) acc[c][j] = 0ull;

        const float* src = &hsrc[(size_t)(R0 + r0) * HH + wid * 128 + k4 * 4];
        float4 vA = __ldcg((const float4*)src);
        float4 vB = __ldcg((const float4*)(src + 4 * HH));
        float4 vC = __ldcg((const float4*)(src + 8 * HH));
        float4 vD = __ldcg((const float4*)(src + 12 * HH));
        int b = 0;

#pragma unroll 1
        for (int ci = 0; ci < 4; ci++) {
            float4 uA, uB, uC, uD;
            if (ci < 3) {   // prefetch next 32-k chunk (in flight during compute)
                const float* s2 = src + (ci + 1) * 32;
                uA = __ldcg((const float4*)s2);
                uB = __ldcg((const float4*)(s2 + 4 * HH));
                uC = __ldcg((const float4*)(s2 + 8 * HH));
                uD = __ldcg((const float4*)(s2 + 12 * HH));
            }
            // stage current chunk: 16 rows x 32 k, row pairs (j, j+4) as u64,
            // 16B slots swizzled by (k>>2)&3 (= k4&3 here)
            {
                ull* dst = hw + b * 256;
                float a[4] = {vA.x, vA.y, vA.z, vA.w};
                float bb[4] = {vB.x, vB.y, vB.z, vB.w};
                float c[4] = {vC.x, vC.y, vC.z, vC.w};
                float d[4] = {vD.x, vD.y, vD.z, vD.w};
#pragma unroll
                for (int e = 0; e < 4; e++) {
                    int kb8 = (k4 * 4 + e) * 8;
                    dst[kb8 + q0w] = pack2(a[e], bb[e]);   // rows (r0, r0+4)
                    dst[kb8 + q1w] = pack2(c[e], d[e]);    // rows (r0+8, r0+12)
                }
            }
            __syncwarp();
            // compute chunk: per k: 2 LDS.128 (h, broadcast) + 1 LDS.64 (w) + 8 FFMA2
            {
                const ull* hb = hw + b * 256;
                const float* wb = &wsm[(wid * 128 + ci * 32) * 32 + 2 * cg];
#pragma unroll
                for (int kk = 0; kk < 32; kk++) {
                    const int m = (kk >> 2) & 3;
                    ulonglong2 hA = *(const ulonglong2*)(hb + kk * 8 + offA[m]); // j = rg2*4+{0,1}
                    ulonglong2 hB = *(const ulonglong2*)(hb + kk * 8 + offB[m]); // j = rg2*4+{2,3}
                    float2 wp = *(const float2*)(wb + kk * 32);
                    ull w0 = pack2(wp.x, wp.x);
                    ull w1 = pack2(wp.y, wp.y);
                    acc[0][0] = fma2(hA.x, w0, acc[0][0]);
                    acc[0][1] = fma2(hA.y, w0, acc[0][1]);
                    acc[0][2] = fma2(hB.x, w0, acc[0][2]);
                    acc[0][3] = fma2(hB.y, w0, acc[0][3]);
                    acc[1][0] = fma2(hA.x, w1, acc[1][0]);
                    acc[1][1] = fma2(hA.y, w1, acc[1][1]);
                    acc[1][2] = fma2(hB.x, w1, acc[1][2]);
                    acc[1][3] = fma2(hB.y, w1, acc[1][3]);
                }
            }
            vA = uA; vB = uB; vC = uC; vD = uD;
            b ^= 1;
            __syncwarp();
        }

        // write this warp's 16x32 partial into red[wid][..]
        // acc[c][j]: rows (rg2*8+j, rg2*8+j+4), col 2cg+c
        {
#pragma unroll
            for (int c = 0; c < 2; c++)
#pragma unroll
                for (int j = 0; j < 4; j++) {
                    float lo, hi;
                    unpack2(acc[c][j], lo, hi);
                    red[wid * 512 + (rg2 * 8 + j) * 32 + 2 * cg + c] = lo;
                    red[wid * 512 + (rg2 * 8 + j + 4) * 32 + 2 * cg + c] = hi;
                }
        }
        __syncthreads();

        // phase 2: sum 8 K-slices + xp, tanh, write h_t over xp_t
        {
            float vv0 = xp0, vv1 = xp1;
#pragma unroll
            for (int q = 0; q < 8; q++) {
                vv0 += red[q * 512 + o0];
                vv1 += red[q * 512 + o1];
            }
            float h0 = tanhf(vv0);
            float h1 = tanhf(vv1);
            xp[gidx0] = h0;
            xp[gidx1] = h1;
            if (write_final && t == TT - 1) {
                out[(size_t)TT * BB * HH + gidx0] = h0;
                out[(size_t)TT * BB * HH + gidx1] = h1;
            }
        }

        if (t < TT - 1) {
            __syncthreads();   // all h_t STGs of this block done
            if (tid == 0)
                asm volatile("st.release.gpu.global.b32 [%0], %1;"
                             :: "l"(myslot), "r"((unsigned)(t + 1)));
            xp0 = xp[BB * HH + gidx0];   // prefetch next xp during wait
            xp1 = xp[BB * HH + gidx1];
            if (wid == 0) {
                unsigned v;
                do {
                    asm volatile("ld.acquire.gpu.global.b32 %0, [%1];"
                                 : "=r"(v) : "l"(po));
                } while (!__all_sync(0xffffffffu, v > (unsigned)t));
            }
            __syncthreads();
        }
    }
}

// ---------------------------------------------------------------------------
extern "C" void kernel_launch(void* const* d_in, const int* in_sizes, int n_in,
                              void* d_out, int out_size) {
    const float* inputs = (const float*)d_in[0];   // [T,B,D]
    const float* state  = (const float*)d_in[1];   // [B,H]
    const float* W_xh   = (const float*)d_in[2];   // [D,H]
    const float* W_hh   = (const float*)d_in[3];   // [H,H]
    const float* b_h    = (const float*)d_in[4];   // [H]
    float* out = (float*)d_out;

    int write_final = (out_size >= TT * BB * HH + BB * HH) ? 1 : 0;

    static int smem_set = 0;
    if (!smem_set) {
        cudaFuncSetAttribute(scan_kernel,
                             cudaFuncAttributeMaxDynamicSharedMemorySize,
                             SM_TOT_B);
        smem_set = 1;
    }

    dim3 g1(HH / 64, (TT * BB) / 128);
    xproj_kernel<<<g1, 256>>>(inputs, W_xh, b_h, out);

    scan_kernel<<<NBLK, NTHR, SM_TOT_B>>>(state, W_hh, out, write_final);
}